// round 14
// baseline (speedup 1.0000x reference)
#include <cuda_runtime.h>
#include <cuda_bf16.h>
#include <cstdint>

#define BATCH 64
#define TIN   128
#define FIN   64
#define HID   512
#define G4    2048
#define TOUTN 64
#define KLIN  32768
#define NLIN  4096

#define KSPLIT 4
#define KPER   (KLIN / KSPLIT)
#define LCHUNK 64
#define LNCH   (KPER / LCHUNK)

// k_step smem (u32 words): W frags | Csm | red
#define WS_OFF  0
#define CSM_OFF 8192
#define RED_OFF (CSM_OFF + 1152)
#define DSMW    (RED_OFF + 1024)    // 10368 u32 = 41472 B

// k_pre1_mma smem (u32 words)
#define P1_AHI 0
#define P1_ALO 4352
#define P1_WHI 8704
#define P1_WLO 17408
#define P1SMW  26112                // 104448 B

__device__ float g_xT[TIN * BATCH * FIN];
__device__ float g_pre1[TIN * BATCH * G4];
__device__ float g_pre2[BATCH * G4];
__device__ float g_hA[BATCH * HID];
__device__ float g_hB[BATCH * HID];
__device__ unsigned short g_hAhi16[BATCH * HID];
__device__ unsigned short g_hAlo16[BATCH * HID];
__device__ unsigned short g_hBhi16[BATCH * HID];
__device__ unsigned short g_hBlo16[BATCH * HID];
__device__ float g_c[BATCH * HID];
__device__ float g_seq[BATCH * KLIN];
__device__ float g_part[KSPLIT * BATCH * NLIN];
__device__ uint32_t g_wf[2][128 * 8192];   // frag-major bf16 hi/lo W planes

__device__ __forceinline__ uint32_t f2tf(float f) {
    uint32_t u;
    asm("cvt.rna.tf32.f32 %0, %1;" : "=r"(u) : "f"(f));
    return u;
}
__device__ __forceinline__ void mma_tf32(float* c, const uint32_t* a, const uint32_t* b) {
    asm volatile(
        "mma.sync.aligned.m16n8k8.row.col.f32.tf32.tf32.f32 "
        "{%0,%1,%2,%3}, {%4,%5,%6,%7}, {%8,%9}, {%0,%1,%2,%3};"
        : "+f"(c[0]), "+f"(c[1]), "+f"(c[2]), "+f"(c[3])
        : "r"(a[0]), "r"(a[1]), "r"(a[2]), "r"(a[3]), "r"(b[0]), "r"(b[1]));
}
__device__ __forceinline__ void mma_bf16(float* c, const uint32_t* a, const uint32_t* b) {
    asm volatile(
        "mma.sync.aligned.m16n8k16.row.col.f32.bf16.bf16.f32 "
        "{%0,%1,%2,%3}, {%4,%5,%6,%7}, {%8,%9}, {%0,%1,%2,%3};"
        : "+f"(c[0]), "+f"(c[1]), "+f"(c[2]), "+f"(c[3])
        : "r"(a[0]), "r"(a[1]), "r"(a[2]), "r"(a[3]), "r"(b[0]), "r"(b[1]));
}
__device__ __forceinline__ uint32_t bf16_split_pack(float x) {
    __nv_bfloat16 h = __float2bfloat16(x);
    float hf = __bfloat162float(h);
    __nv_bfloat16 l = __float2bfloat16(x - hf);
    return (uint32_t)__bfloat16_as_ushort(h) |
           ((uint32_t)__bfloat16_as_ushort(l) << 16);
}

// ---------------- small kernels ----------------
__global__ void k_xt(const float* __restrict__ x) {
    int i = blockIdx.x * 256 + threadIdx.x;
    if (i < TIN * BATCH * FIN) {
        int k = i & 63, r = i >> 6;
        int t = r >> 6, b = r & 63;
        g_xT[i] = x[(b * TIN + t) * FIN + k];
    }
}
__global__ void k_init() {
    int i = blockIdx.x * 256 + threadIdx.x;
    if (i < BATCH * HID) {
        g_hAhi16[i] = 0; g_hAlo16[i] = 0; g_c[i] = 0.0f;
    }
}
__global__ void k_combine(const float* __restrict__ blin, float* __restrict__ out) {
    int i = blockIdx.x * 256 + threadIdx.x;
    if (i < BATCH * NLIN) {
        int b = i >> 12, m = i & 4095;
        float s = blin[m];
#pragma unroll
        for (int ks = 0; ks < KSPLIT; ++ks)
            s += g_part[((size_t)ks * BATCH + b) * NLIN + m];
        out[i] = s;
    }
}

// ---------------- W frag prep (R10-verified layout) ----------------
__global__ void __launch_bounds__(256) k_prepW(const float* __restrict__ W1,
                                               const float* __restrict__ W2) {
    int layer = blockIdx.x >> 7;
    int bk = blockIdx.x & 127;
    const float* Whh = layer ? W2 : W1;
    uint32_t* dst = g_wf[layer] + (size_t)bk * 8192;
    int hc0 = bk * 4;
    for (int idx = threadIdx.x; idx < 8192; idx += 256) {
        int fragId = idx >> 6, rem = idx & 63;
        int ln = rem >> 1, rg = rem & 1;
        int plane = fragId & 1, nt = (fragId >> 1) & 1, ktile = fragId >> 2;
        int n = nt * 8 + (ln >> 2);
        int q = n >> 2, cc = n & 3;
        int k = ktile * 16 + (ln & 3) * 2 + rg * 8;
        const float* wr = Whh + (size_t)(q * HID + hc0 + cc) * HID + k;
        uint32_t p0 = bf16_split_pack(wr[0]);
        uint32_t p1 = bf16_split_pack(wr[1]);
        dst[idx] = (plane == 0) ? __byte_perm(p0, p1, 0x5410)
                                : __byte_perm(p0, p1, 0x7632);
    }
}

// ---------------- tf32 hi/lo mma pre1: g_pre1 = g_xT @ Wih1^T + biases ----------------
// block: 64 x-rows (blockIdx.y) x 128 gate-cols (blockIdx.x), K=64.
__global__ void __launch_bounds__(256, 1) k_pre1_mma(const float* __restrict__ W,
                                                     const float* __restrict__ b1,
                                                     const float* __restrict__ b2) {
    extern __shared__ __align__(16) uint32_t psm[];
    uint32_t* Ahi = psm + P1_AHI;
    uint32_t* Alo = psm + P1_ALO;
    uint32_t* Whi = psm + P1_WHI;
    uint32_t* Wlo = psm + P1_WLO;
    const int tid = threadIdx.x, wid = tid >> 5, lane = tid & 31;
    const int gid = lane >> 2, tig = lane & 3;
    const int n0 = blockIdx.x * 128;
    const int m0 = blockIdx.y * 64;

    // stage A (64x64 f32 -> hi/lo)
#pragma unroll
    for (int e = 0; e < 4; ++e) {
        int idx = tid + e * 256, row = idx >> 4, c4 = idx & 15;
        float4 v = *(const float4*)(g_xT + (size_t)(m0 + row) * FIN + c4 * 4);
        uint32_t* dh = Ahi + row * 68 + c4 * 4;
        uint32_t* dl = Alo + row * 68 + c4 * 4;
        uint32_t h0 = f2tf(v.x), h1 = f2tf(v.y), h2 = f2tf(v.z), h3 = f2tf(v.w);
        dh[0] = h0; dh[1] = h1; dh[2] = h2; dh[3] = h3;
        dl[0] = f2tf(v.x - __uint_as_float(h0));
        dl[1] = f2tf(v.y - __uint_as_float(h1));
        dl[2] = f2tf(v.z - __uint_as_float(h2));
        dl[3] = f2tf(v.w - __uint_as_float(h3));
    }
    // stage W (128x64 f32 -> hi/lo)
#pragma unroll
    for (int e = 0; e < 8; ++e) {
        int idx = tid + e * 256, row = idx >> 4, c4 = idx & 15;
        float4 v = *(const float4*)(W + (size_t)(n0 + row) * FIN + c4 * 4);
        uint32_t* dh = Whi + row * 68 + c4 * 4;
        uint32_t* dl = Wlo + row * 68 + c4 * 4;
        uint32_t h0 = f2tf(v.x), h1 = f2tf(v.y), h2 = f2tf(v.z), h3 = f2tf(v.w);
        dh[0] = h0; dh[1] = h1; dh[2] = h2; dh[3] = h3;
        dl[0] = f2tf(v.x - __uint_as_float(h0));
        dl[1] = f2tf(v.y - __uint_as_float(h1));
        dl[2] = f2tf(v.z - __uint_as_float(h2));
        dl[3] = f2tf(v.w - __uint_as_float(h3));
    }
    __syncthreads();

    float acc[4][2][4];
#pragma unroll
    for (int mt = 0; mt < 4; ++mt)
#pragma unroll
        for (int nt = 0; nt < 2; ++nt)
#pragma unroll
            for (int r = 0; r < 4; ++r) acc[mt][nt][r] = 0.0f;

#pragma unroll
    for (int kk = 0; kk < 8; ++kk) {
        uint32_t ah[4][4], al[4][4], bh[2][2], bl[2][2];
#pragma unroll
        for (int mt = 0; mt < 4; ++mt) {
            int ab = (mt * 16 + gid) * 68 + kk * 8 + tig;
            ah[mt][0] = Ahi[ab];           ah[mt][1] = Ahi[ab + 8 * 68];
            ah[mt][2] = Ahi[ab + 4];       ah[mt][3] = Ahi[ab + 8 * 68 + 4];
            al[mt][0] = Alo[ab];           al[mt][1] = Alo[ab + 8 * 68];
            al[mt][2] = Alo[ab + 4];       al[mt][3] = Alo[ab + 8 * 68 + 4];
        }
#pragma unroll
        for (int nt = 0; nt < 2; ++nt) {
            int bb = (wid * 16 + nt * 8 + gid) * 68 + kk * 8 + tig;
            bh[nt][0] = Whi[bb];  bh[nt][1] = Whi[bb + 4];
            bl[nt][0] = Wlo[bb];  bl[nt][1] = Wlo[bb + 4];
        }
#pragma unroll
        for (int mt = 0; mt < 4; ++mt)
#pragma unroll
            for (int nt = 0; nt < 2; ++nt) {
                mma_tf32(acc[mt][nt], ah[mt], bh[nt]);
                mma_tf32(acc[mt][nt], ah[mt], bl[nt]);
                mma_tf32(acc[mt][nt], al[mt], bh[nt]);
            }
    }

#pragma unroll
    for (int mt = 0; mt < 4; ++mt) {
#pragma unroll
        for (int nt = 0; nt < 2; ++nt) {
            int m = m0 + mt * 16 + gid;
            int n = n0 + wid * 16 + nt * 8 + 2 * tig;
            float bias0 = b1[n] + b2[n], bias1v = b1[n + 1] + b2[n + 1];
            *(float2*)(g_pre1 + (size_t)m * G4 + n) =
                make_float2(acc[mt][nt][0] + bias0, acc[mt][nt][1] + bias1v);
            *(float2*)(g_pre1 + (size_t)(m + 8) * G4 + n) =
                make_float2(acc[mt][nt][2] + bias0, acc[mt][nt][3] + bias1v);
        }
    }
}

// ---------------- fp32 SIMT GEMM (pre2 only, proven) ----------------
__device__ __forceinline__ void gemm64_core(
    const float* __restrict__ A, int lda,
    const float* __restrict__ W, int ldw,
    float* __restrict__ C, int ldc, int kcount,
    const float* __restrict__ bias1, const float* __restrict__ bias2)
{
    __shared__ __align__(16) float As[2][32 * 68];
    __shared__ __align__(16) float Ws[2][32 * 68];
    const int tid = threadIdx.x;
    const int n0 = blockIdx.x * 64;
    const int mbase = blockIdx.z * 64;
    const int b0 = (tid & 15) * 4, nt = (tid >> 4) * 4;
    float acc[4][4];
#pragma unroll
    for (int i = 0; i < 4; ++i)
#pragma unroll
        for (int j = 0; j < 4; ++j) acc[i][j] = 0.0f;
    const int ntiles = kcount >> 5;
#pragma unroll
    for (int e = 0; e < 8; ++e) {
        int idx = tid + e * 256, m = idx >> 5, k = idx & 31;
        As[0][k * 68 + m] = A[(size_t)(mbase + m) * lda + k];
        Ws[0][k * 68 + m] = W[(size_t)(n0 + m) * ldw + k];
    }
    __syncthreads();
    for (int kt = 0; kt < ntiles; ++kt) {
        float pfA[8], pfW[8];
        const bool more = (kt + 1 < ntiles);
        if (more) {
            int ko = (kt + 1) << 5;
#pragma unroll
            for (int e = 0; e < 8; ++e) {
                int idx = tid + e * 256, m = idx >> 5, k = idx & 31;
                pfA[e] = A[(size_t)(mbase + m) * lda + ko + k];
                pfW[e] = W[(size_t)(n0 + m) * ldw + ko + k];
            }
        }
        const float* as = As[kt & 1];
        const float* wz = Ws[kt & 1];
#pragma unroll
        for (int k = 0; k < 32; ++k) {
            float4 av = *(const float4*)(as + k * 68 + b0);
            float4 wv = *(const float4*)(wz + k * 68 + nt);
            float aa[4] = {av.x, av.y, av.z, av.w};
            float ww[4] = {wv.x, wv.y, wv.z, wv.w};
#pragma unroll
            for (int i = 0; i < 4; ++i)
#pragma unroll
                for (int j = 0; j < 4; ++j)
                    acc[i][j] = fmaf(aa[i], ww[j], acc[i][j]);
        }
        if (more) {
            float* dA = As[(kt + 1) & 1];
            float* dW = Ws[(kt + 1) & 1];
#pragma unroll
            for (int e = 0; e < 8; ++e) {
                int idx = tid + e * 256, m = idx >> 5, k = idx & 31;
                dA[k * 68 + m] = pfA[e];
                dW[k * 68 + m] = pfW[e];
            }
        }
        __syncthreads();
    }
#pragma unroll
    for (int i = 0; i < 4; ++i) {
        int m = mbase + b0 + i;
#pragma unroll
        for (int j = 0; j < 4; ++j) {
            int n = n0 + nt + j;
            C[(size_t)m * ldc + n] = acc[i][j] + bias1[n] + bias2[n];
        }
    }
}
__global__ void __launch_bounds__(256) k_pre2(const float* __restrict__ W,
                                              const float* __restrict__ b1,
                                              const float* __restrict__ b2) {
    gemm64_core(g_hA, HID, W, HID, g_pre2, G4, HID, b1, b2);
}

// ---------------- tf32 mma.sync linear (proven R7/R8) ----------------
__global__ void __launch_bounds__(256, 1) k_lin_mma(const float* __restrict__ Wl) {
    extern __shared__ __align__(16) uint32_t lsm[];
    const int tid = threadIdx.x, wid = tid >> 5, lane = tid & 31;
    const int gid = lane >> 2, tig = lane & 3;
    const int m0 = blockIdx.x * 128;
    const int ks = blockIdx.y;
    const int k0b = ks * KPER;

    float acc[4][2][4];
#pragma unroll
    for (int mt = 0; mt < 4; ++mt)
#pragma unroll
        for (int nt = 0; nt < 2; ++nt)
#pragma unroll
            for (int r = 0; r < 4; ++r) acc[mt][nt][r] = 0.0f;
    {
        uint32_t* A0 = lsm;
        uint32_t* W0 = lsm + 4352;
#pragma unroll
        for (int e = 0; e < 4; ++e) {
            int idx = tid + e * 256, row = idx >> 4, c4 = idx & 15;
            float4 v = *(const float4*)(g_seq + (size_t)row * KLIN + k0b + c4 * 4);
            uint32_t* d = A0 + row * 68 + c4 * 4;
            d[0] = f2tf(v.x); d[1] = f2tf(v.y); d[2] = f2tf(v.z); d[3] = f2tf(v.w);
        }
#pragma unroll
        for (int e = 0; e < 8; ++e) {
            int idx = tid + e * 256, row = idx >> 4, c4 = idx & 15;
            float4 v = *(const float4*)(Wl + (size_t)(m0 + row) * KLIN + k0b + c4 * 4);
            uint32_t* d = W0 + row * 68 + c4 * 4;
            d[0] = f2tf(v.x); d[1] = f2tf(v.y); d[2] = f2tf(v.z); d[3] = f2tf(v.w);
        }
    }
    __syncthreads();

    for (int ch = 0; ch < LNCH; ++ch) {
        const int buf = ch & 1;
        const bool more = (ch + 1 < LNCH);
        float4 fa[4], fw[8];
        if (more) {
            int k0 = k0b + (ch + 1) * LCHUNK;
#pragma unroll
            for (int e = 0; e < 4; ++e) {
                int idx = tid + e * 256, row = idx >> 4, c4 = idx & 15;
                fa[e] = *(const float4*)(g_seq + (size_t)row * KLIN + k0 + c4 * 4);
            }
#pragma unroll
            for (int e = 0; e < 8; ++e) {
                int idx = tid + e * 256, row = idx >> 4, c4 = idx & 15;
                fw[e] = *(const float4*)(Wl + (size_t)(m0 + row) * KLIN + k0 + c4 * 4);
            }
        }
        const uint32_t* As = lsm + buf * 13056;
        const uint32_t* Ws = lsm + buf * 13056 + 4352;
#pragma unroll
        for (int kk = 0; kk < 8; ++kk) {
            uint32_t a[4][4], b[2][2];
#pragma unroll
            for (int mt = 0; mt < 4; ++mt) {
                const uint32_t* ap = As + (mt * 16 + gid) * 68 + kk * 8 + tig;
                a[mt][0] = ap[0];
                a[mt][1] = ap[8 * 68];
                a[mt][2] = ap[4];
                a[mt][3] = ap[8 * 68 + 4];
            }
#pragma unroll
            for (int nt = 0; nt < 2; ++nt) {
                const uint32_t* bp = Ws + (wid * 16 + nt * 8 + gid) * 68 + kk * 8 + tig;
                b[nt][0] = bp[0];
                b[nt][1] = bp[4];
            }
#pragma unroll
            for (int mt = 0; mt < 4; ++mt)
#pragma unroll
                for (int nt = 0; nt < 2; ++nt)
                    mma_tf32(acc[mt][nt], a[mt], b[nt]);
        }
        if (more) {
            uint32_t* A1 = lsm + (buf ^ 1) * 13056;
            uint32_t* W1 = A1 + 4352;
#pragma unroll
            for (int e = 0; e < 4; ++e) {
                int idx = tid + e * 256, row = idx >> 4, c4 = idx & 15;
                uint32_t* d = A1 + row * 68 + c4 * 4;
                d[0] = f2tf(fa[e].x); d[1] = f2tf(fa[e].y);
                d[2] = f2tf(fa[e].z); d[3] = f2tf(fa[e].w);
            }
#pragma unroll
            for (int e = 0; e < 8; ++e) {
                int idx = tid + e * 256, row = idx >> 4, c4 = idx & 15;
                uint32_t* d = W1 + row * 68 + c4 * 4;
                d[0] = f2tf(fw[e].x); d[1] = f2tf(fw[e].y);
                d[2] = f2tf(fw[e].z); d[3] = f2tf(fw[e].w);
            }
        }
        __syncthreads();
    }
#pragma unroll
    for (int mt = 0; mt < 4; ++mt) {
#pragma unroll
        for (int nt = 0; nt < 2; ++nt) {
            int brow = mt * 16 + gid;
            int m = m0 + wid * 16 + nt * 8 + 2 * tig;
            float* base0 = &g_part[((size_t)ks * BATCH + brow) * NLIN + m];
            float* base1 = &g_part[((size_t)ks * BATCH + brow + 8) * NLIN + m];
            *(float2*)base0 = make_float2(acc[mt][nt][0], acc[mt][nt][1]);
            *(float2*)base1 = make_float2(acc[mt][nt][2], acc[mt][nt][3]);
        }
    }
}

// ---------------- one LSTM time-step per launch ----------------
// A frags read DIRECTLY from global h planes (each element consumed exactly
// once per block per step); W frags staged once to smem (4 warps share them).
__global__ void __launch_bounds__(256, 1) k_step(int layer, int t, int loadC,
                                                 int writeSeq, int writeF) {
    extern __shared__ __align__(16) uint32_t sm[];
    uint32_t* wsf = sm + WS_OFF;
    float* Csm = (float*)(sm + CSM_OFF);
    float* red = (float*)(sm + RED_OFF);

    const int tid = threadIdx.x;
    const int bk = blockIdx.x;
    const int hc0 = bk * 4;
    const int lane = tid & 31, wid = tid >> 5;
    const int mg = wid >> 1, kh = wid & 1;
    const int gid = lane >> 2, tig = lane & 3;
    const int b = tid & 63, chn = (tid >> 6) & 3;
    const int hcol = hc0 + chn;

    const unsigned short* hinHi = (t & 1) ? g_hBhi16 : g_hAhi16;
    const unsigned short* hinLo = (t & 1) ? g_hBlo16 : g_hAlo16;
    unsigned short* houtHi = (t & 1) ? g_hAhi16 : g_hBhi16;
    unsigned short* houtLo = (t & 1) ? g_hAlo16 : g_hBlo16;
    float* houtF = (t & 1) ? g_hA : g_hB;
    const float* pre = layer ? (g_pre2 + b * G4 + hcol)
                             : (g_pre1 + (size_t)t * (BATCH * G4) + b * G4 + hcol);

    // stage W frags (32 KB)
    {
        const uint4* wsrc = (const uint4*)(g_wf[layer] + (size_t)bk * 8192);
        uint4* wdst = (uint4*)wsf;
#pragma unroll
        for (int e = 0; e < 8; ++e)
            wdst[tid + e * 256] = __ldcg(wsrc + tid + e * 256);
    }
    float p0 = __ldg(pre), p1 = __ldg(pre + 512);
    float p2 = __ldg(pre + 1024), p3 = __ldg(pre + 1536);
    float creg = loadC ? g_c[b * HID + hcol] : 0.0f;
    __syncthreads();

    const uint32_t* hi32 = (const uint32_t*)hinHi;   // 64 rows x 256 u32
    const uint32_t* lo32 = (const uint32_t*)hinLo;
    const int arow = (mg * 16 + gid) * 256;

    float acc[2][4];
#pragma unroll
    for (int nt = 0; nt < 2; ++nt)
#pragma unroll
        for (int r = 0; r < 4; ++r) acc[nt][r] = 0.f;

#pragma unroll
    for (int kt = 0; kt < 16; ++kt) {
        int ktg = kh * 16 + kt;
        int ab = arow + ktg * 8 + tig;
        uint32_t ah[4], al[4];
        ah[0] = __ldcg(hi32 + ab);          ah[1] = __ldcg(hi32 + ab + 2048);
        ah[2] = __ldcg(hi32 + ab + 4);      ah[3] = __ldcg(hi32 + ab + 2052);
        al[0] = __ldcg(lo32 + ab);          al[1] = __ldcg(lo32 + ab + 2048);
        al[2] = __ldcg(lo32 + ab + 4);      al[3] = __ldcg(lo32 + ab + 2052);
#pragma unroll
        for (int nt = 0; nt < 2; ++nt) {
            int fb = ((ktg * 2 + nt) * 2) * 64 + lane * 2;
            uint32_t bh[2], bl[2];
            *(uint2*)bh = *(const uint2*)(wsf + fb);
            *(uint2*)bl = *(const uint2*)(wsf + fb + 64);
            mma_bf16(acc[nt], ah, bh);
            mma_bf16(acc[nt], ah, bl);
            mma_bf16(acc[nt], al, bh);
        }
    }

    if (kh == 1) {
#pragma unroll
        for (int nt = 0; nt < 2; ++nt)
            *(float4*)(red + (mg * 32 + lane) * 8 + nt * 4) =
                make_float4(acc[nt][0], acc[nt][1], acc[nt][2], acc[nt][3]);
    }
    __syncthreads();
    if (kh == 0) {
#pragma unroll
        for (int nt = 0; nt < 2; ++nt) {
            float4 r4 = *(const float4*)(red + (mg * 32 + lane) * 8 + nt * 4);
            int row = mg * 16 + gid, col = nt * 8 + 2 * tig;
            Csm[row * 17 + col]           = acc[nt][0] + r4.x;
            Csm[row * 17 + col + 1]       = acc[nt][1] + r4.y;
            Csm[(row + 8) * 17 + col]     = acc[nt][2] + r4.z;
            Csm[(row + 8) * 17 + col + 1] = acc[nt][3] + r4.w;
        }
    }
    __syncthreads();

    {
        float a0 = Csm[b * 17 + 0 + chn] + p0;
        float a1 = Csm[b * 17 + 4 + chn] + p1;
        float a2 = Csm[b * 17 + 8 + chn] + p2;
        float a3 = Csm[b * 17 + 12 + chn] + p3;
        float si = 1.f / (1.f + __expf(-a0));
        float sf = 1.f / (1.f + __expf(-a1));
        float so = 1.f / (1.f + __expf(-a3));
        creg = sf * creg + si * tanhf(a2);
        float hnew = so * tanhf(creg);
        g_c[b * HID + hcol] = creg;
        __nv_bfloat16 hh = __float2bfloat16(hnew);
        __nv_bfloat16 hl = __float2bfloat16(hnew - __bfloat162float(hh));
        houtHi[b * HID + hcol] = __bfloat16_as_ushort(hh);
        houtLo[b * HID + hcol] = __bfloat16_as_ushort(hl);
        if (writeF) houtF[b * HID + hcol] = hnew;
        if (writeSeq) g_seq[(size_t)b * KLIN + t * HID + hcol] = hnew;
    }
}

extern "C" void kernel_launch(void* const* d_in, const int* in_sizes, int n_in,
                              void* d_out, int out_size) {
    const float* x    = (const float*)d_in[0];
    const float* Wih1 = (const float*)d_in[1];
    const float* Whh1 = (const float*)d_in[2];
    const float* bih1 = (const float*)d_in[3];
    const float* bhh1 = (const float*)d_in[4];
    const float* Wih2 = (const float*)d_in[5];
    const float* Whh2 = (const float*)d_in[6];
    const float* bih2 = (const float*)d_in[7];
    const float* bhh2 = (const float*)d_in[8];
    const float* Wlin = (const float*)d_in[9];
    const float* blin = (const float*)d_in[10];
    float* out = (float*)d_out;

    const int stepSmem = DSMW * 4;        // 41472
    const int linSmem  = 2 * 13056 * 4;   // 104448
    const int p1Smem   = P1SMW * 4;       // 104448
    cudaFuncSetAttribute(k_step, cudaFuncAttributeMaxDynamicSharedMemorySize, stepSmem);
    cudaFuncSetAttribute(k_lin_mma, cudaFuncAttributeMaxDynamicSharedMemorySize, linSmem);
    cudaFuncSetAttribute(k_pre1_mma, cudaFuncAttributeMaxDynamicSharedMemorySize, p1Smem);

    k_xt<<<(TIN * BATCH * FIN + 255) / 256, 256>>>(x);
    k_init<<<(BATCH * HID + 255) / 256, 256>>>();
    k_prepW<<<256, 256>>>(Whh1, Whh2);

    dim3 gpre1(G4 / 128, (TIN * BATCH) / 64);
    k_pre1_mma<<<gpre1, 256, p1Smem>>>(Wih1, bih1, bhh1);

    for (int t = 0; t < TIN; ++t)
        k_step<<<128, 256, stepSmem>>>(0, t, t > 0 ? 1 : 0, 0,
                                       (t == TIN - 1) ? 1 : 0);
    // TIN=128 even -> final h f32 in g_hA (t=127 odd => houtF=g_hA), c in g_c

    dim3 gpre2(G4 / 64, 1, 1);
    k_pre2<<<gpre2, 256>>>(Wih2, bih2, bhh2);

    for (int t = 0; t < TOUTN; ++t)
        k_step<<<128, 256, stepSmem>>>(1, t, 1, 1, 0);

    dim3 glin(NLIN / 128, KSPLIT);
    k_lin_mma<<<glin, 256, linSmem>>>(Wlin);

    k_combine<<<(BATCH * NLIN + 255) / 256, 256>>>(blin, out);
}

// round 15
// speedup vs baseline: 1.4627x; 1.4627x over previous
#include <cuda_runtime.h>
#include <cuda_bf16.h>
#include <cstdint>

#define BATCH 64
#define TIN   128
#define FIN   64
#define HID   512
#define G4    2048
#define TOUTN 64
#define KLIN  32768
#define NLIN  4096

#define KSPLIT 4
#define KPER   (KLIN / KSPLIT)
#define LCHUNK 64
#define LNCH   (KPER / LCHUNK)

// k_step smem (u32 words)
#define WS_OFF  0
#define AHI_OFF 8192
#define ALO_OFF (AHI_OFF + 16640)
#define CSM_OFF (ALO_OFF + 16640)
#define RED_OFF (CSM_OFF + 1152)
#define DSMW    (RED_OFF + 1024)    // 43648 u32 = 174592 B

// k_pre1_mma smem (u32 words)
#define P1_AHI 0
#define P1_ALO 4352
#define P1_WHI 8704
#define P1_WLO 17408
#define P1SMW  26112                // 104448 B

__device__ float g_xT[TIN * BATCH * FIN];
__device__ float g_pre1[TIN * BATCH * G4];
__device__ float g_pre2[BATCH * G4];
__device__ float g_hA[BATCH * HID];
__device__ float g_hB[BATCH * HID];
__device__ unsigned short g_hAhi16[BATCH * HID];
__device__ unsigned short g_hAlo16[BATCH * HID];
__device__ unsigned short g_hBhi16[BATCH * HID];
__device__ unsigned short g_hBlo16[BATCH * HID];
__device__ float g_c[BATCH * HID];
__device__ float g_seq[BATCH * KLIN];
__device__ float g_part[KSPLIT * BATCH * NLIN];
__device__ uint32_t g_wf[2][128 * 8192];   // frag-major bf16 hi/lo W planes

__device__ __forceinline__ uint32_t f2tf(float f) {
    uint32_t u;
    asm("cvt.rna.tf32.f32 %0, %1;" : "=r"(u) : "f"(f));
    return u;
}
__device__ __forceinline__ void mma_tf32(float* c, const uint32_t* a, const uint32_t* b) {
    asm volatile(
        "mma.sync.aligned.m16n8k8.row.col.f32.tf32.tf32.f32 "
        "{%0,%1,%2,%3}, {%4,%5,%6,%7}, {%8,%9}, {%0,%1,%2,%3};"
        : "+f"(c[0]), "+f"(c[1]), "+f"(c[2]), "+f"(c[3])
        : "r"(a[0]), "r"(a[1]), "r"(a[2]), "r"(a[3]), "r"(b[0]), "r"(b[1]));
}
__device__ __forceinline__ void mma_bf16(float* c, const uint32_t* a, const uint32_t* b) {
    asm volatile(
        "mma.sync.aligned.m16n8k16.row.col.f32.bf16.bf16.f32 "
        "{%0,%1,%2,%3}, {%4,%5,%6,%7}, {%8,%9}, {%0,%1,%2,%3};"
        : "+f"(c[0]), "+f"(c[1]), "+f"(c[2]), "+f"(c[3])
        : "r"(a[0]), "r"(a[1]), "r"(a[2]), "r"(a[3]), "r"(b[0]), "r"(b[1]));
}
__device__ __forceinline__ uint32_t bf16_split_pack(float x) {
    __nv_bfloat16 h = __float2bfloat16(x);
    float hf = __bfloat162float(h);
    __nv_bfloat16 l = __float2bfloat16(x - hf);
    return (uint32_t)__bfloat16_as_ushort(h) |
           ((uint32_t)__bfloat16_as_ushort(l) << 16);
}

// ---------------- small kernels ----------------
__global__ void k_xt(const float* __restrict__ x) {
    int i = blockIdx.x * 256 + threadIdx.x;
    if (i < TIN * BATCH * FIN) {
        int k = i & 63, r = i >> 6;
        int t = r >> 6, b = r & 63;
        g_xT[i] = x[(b * TIN + t) * FIN + k];
    }
}
__global__ void k_init() {
    int i = blockIdx.x * 256 + threadIdx.x;
    if (i < BATCH * HID) {
        g_hAhi16[i] = 0; g_hAlo16[i] = 0; g_c[i] = 0.0f;
    }
}
__global__ void k_combine(const float* __restrict__ blin, float* __restrict__ out) {
    int i = blockIdx.x * 256 + threadIdx.x;
    if (i < BATCH * NLIN) {
        int b = i >> 12, m = i & 4095;
        float s = blin[m];
#pragma unroll
        for (int ks = 0; ks < KSPLIT; ++ks)
            s += g_part[((size_t)ks * BATCH + b) * NLIN + m];
        out[i] = s;
    }
}

// ---------------- W frag prep (R10-verified layout) ----------------
__global__ void __launch_bounds__(256) k_prepW(const float* __restrict__ W1,
                                               const float* __restrict__ W2) {
    int layer = blockIdx.x >> 7;
    int bk = blockIdx.x & 127;
    const float* Whh = layer ? W2 : W1;
    uint32_t* dst = g_wf[layer] + (size_t)bk * 8192;
    int hc0 = bk * 4;
    for (int idx = threadIdx.x; idx < 8192; idx += 256) {
        int fragId = idx >> 6, rem = idx & 63;
        int ln = rem >> 1, rg = rem & 1;
        int plane = fragId & 1, nt = (fragId >> 1) & 1, ktile = fragId >> 2;
        int n = nt * 8 + (ln >> 2);
        int q = n >> 2, cc = n & 3;
        int k = ktile * 16 + (ln & 3) * 2 + rg * 8;
        const float* wr = Whh + (size_t)(q * HID + hc0 + cc) * HID + k;
        uint32_t p0 = bf16_split_pack(wr[0]);
        uint32_t p1 = bf16_split_pack(wr[1]);
        dst[idx] = (plane == 0) ? __byte_perm(p0, p1, 0x5410)
                                : __byte_perm(p0, p1, 0x7632);
    }
}

// ---------------- tf32 hi/lo mma pre1 (R14-verified: 50us, fp32-grade) ----------------
__global__ void __launch_bounds__(256, 1) k_pre1_mma(const float* __restrict__ W,
                                                     const float* __restrict__ b1,
                                                     const float* __restrict__ b2) {
    extern __shared__ __align__(16) uint32_t psm[];
    uint32_t* Ahi = psm + P1_AHI;
    uint32_t* Alo = psm + P1_ALO;
    uint32_t* Whi = psm + P1_WHI;
    uint32_t* Wlo = psm + P1_WLO;
    const int tid = threadIdx.x, wid = tid >> 5, lane = tid & 31;
    const int gid = lane >> 2, tig = lane & 3;
    const int n0 = blockIdx.x * 128;
    const int m0 = blockIdx.y * 64;

#pragma unroll
    for (int e = 0; e < 4; ++e) {
        int idx = tid + e * 256, row = idx >> 4, c4 = idx & 15;
        float4 v = *(const float4*)(g_xT + (size_t)(m0 + row) * FIN + c4 * 4);
        uint32_t* dh = Ahi + row * 68 + c4 * 4;
        uint32_t* dl = Alo + row * 68 + c4 * 4;
        uint32_t h0 = f2tf(v.x), h1 = f2tf(v.y), h2 = f2tf(v.z), h3 = f2tf(v.w);
        dh[0] = h0; dh[1] = h1; dh[2] = h2; dh[3] = h3;
        dl[0] = f2tf(v.x - __uint_as_float(h0));
        dl[1] = f2tf(v.y - __uint_as_float(h1));
        dl[2] = f2tf(v.z - __uint_as_float(h2));
        dl[3] = f2tf(v.w - __uint_as_float(h3));
    }
#pragma unroll
    for (int e = 0; e < 8; ++e) {
        int idx = tid + e * 256, row = idx >> 4, c4 = idx & 15;
        float4 v = *(const float4*)(W + (size_t)(n0 + row) * FIN + c4 * 4);
        uint32_t* dh = Whi + row * 68 + c4 * 4;
        uint32_t* dl = Wlo + row * 68 + c4 * 4;
        uint32_t h0 = f2tf(v.x), h1 = f2tf(v.y), h2 = f2tf(v.z), h3 = f2tf(v.w);
        dh[0] = h0; dh[1] = h1; dh[2] = h2; dh[3] = h3;
        dl[0] = f2tf(v.x - __uint_as_float(h0));
        dl[1] = f2tf(v.y - __uint_as_float(h1));
        dl[2] = f2tf(v.z - __uint_as_float(h2));
        dl[3] = f2tf(v.w - __uint_as_float(h3));
    }
    __syncthreads();

    float acc[4][2][4];
#pragma unroll
    for (int mt = 0; mt < 4; ++mt)
#pragma unroll
        for (int nt = 0; nt < 2; ++nt)
#pragma unroll
            for (int r = 0; r < 4; ++r) acc[mt][nt][r] = 0.0f;

#pragma unroll
    for (int kk = 0; kk < 8; ++kk) {
        uint32_t ah[4][4], al[4][4], bh[2][2], bl[2][2];
#pragma unroll
        for (int mt = 0; mt < 4; ++mt) {
            int ab = (mt * 16 + gid) * 68 + kk * 8 + tig;
            ah[mt][0] = Ahi[ab];           ah[mt][1] = Ahi[ab + 8 * 68];
            ah[mt][2] = Ahi[ab + 4];       ah[mt][3] = Ahi[ab + 8 * 68 + 4];
            al[mt][0] = Alo[ab];           al[mt][1] = Alo[ab + 8 * 68];
            al[mt][2] = Alo[ab + 4];       al[mt][3] = Alo[ab + 8 * 68 + 4];
        }
#pragma unroll
        for (int nt = 0; nt < 2; ++nt) {
            int bb = (wid * 16 + nt * 8 + gid) * 68 + kk * 8 + tig;
            bh[nt][0] = Whi[bb];  bh[nt][1] = Whi[bb + 4];
            bl[nt][0] = Wlo[bb];  bl[nt][1] = Wlo[bb + 4];
        }
#pragma unroll
        for (int mt = 0; mt < 4; ++mt)
#pragma unroll
            for (int nt = 0; nt < 2; ++nt) {
                mma_tf32(acc[mt][nt], ah[mt], bh[nt]);
                mma_tf32(acc[mt][nt], ah[mt], bl[nt]);
                mma_tf32(acc[mt][nt], al[mt], bh[nt]);
            }
    }

#pragma unroll
    for (int mt = 0; mt < 4; ++mt) {
#pragma unroll
        for (int nt = 0; nt < 2; ++nt) {
            int m = m0 + mt * 16 + gid;
            int n = n0 + wid * 16 + nt * 8 + 2 * tig;
            float bias0 = b1[n] + b2[n], bias1v = b1[n + 1] + b2[n + 1];
            *(float2*)(g_pre1 + (size_t)m * G4 + n) =
                make_float2(acc[mt][nt][0] + bias0, acc[mt][nt][1] + bias1v);
            *(float2*)(g_pre1 + (size_t)(m + 8) * G4 + n) =
                make_float2(acc[mt][nt][2] + bias0, acc[mt][nt][3] + bias1v);
        }
    }
}

// ---------------- fp32 SIMT GEMM (pre2 only, proven) ----------------
__device__ __forceinline__ void gemm64_core(
    const float* __restrict__ A, int lda,
    const float* __restrict__ W, int ldw,
    float* __restrict__ C, int ldc, int kcount,
    const float* __restrict__ bias1, const float* __restrict__ bias2)
{
    __shared__ __align__(16) float As[2][32 * 68];
    __shared__ __align__(16) float Ws[2][32 * 68];
    const int tid = threadIdx.x;
    const int n0 = blockIdx.x * 64;
    const int mbase = blockIdx.z * 64;
    const int b0 = (tid & 15) * 4, nt = (tid >> 4) * 4;
    float acc[4][4];
#pragma unroll
    for (int i = 0; i < 4; ++i)
#pragma unroll
        for (int j = 0; j < 4; ++j) acc[i][j] = 0.0f;
    const int ntiles = kcount >> 5;
#pragma unroll
    for (int e = 0; e < 8; ++e) {
        int idx = tid + e * 256, m = idx >> 5, k = idx & 31;
        As[0][k * 68 + m] = A[(size_t)(mbase + m) * lda + k];
        Ws[0][k * 68 + m] = W[(size_t)(n0 + m) * ldw + k];
    }
    __syncthreads();
    for (int kt = 0; kt < ntiles; ++kt) {
        float pfA[8], pfW[8];
        const bool more = (kt + 1 < ntiles);
        if (more) {
            int ko = (kt + 1) << 5;
#pragma unroll
            for (int e = 0; e < 8; ++e) {
                int idx = tid + e * 256, m = idx >> 5, k = idx & 31;
                pfA[e] = A[(size_t)(mbase + m) * lda + ko + k];
                pfW[e] = W[(size_t)(n0 + m) * ldw + ko + k];
            }
        }
        const float* as = As[kt & 1];
        const float* wz = Ws[kt & 1];
#pragma unroll
        for (int k = 0; k < 32; ++k) {
            float4 av = *(const float4*)(as + k * 68 + b0);
            float4 wv = *(const float4*)(wz + k * 68 + nt);
            float aa[4] = {av.x, av.y, av.z, av.w};
            float ww[4] = {wv.x, wv.y, wv.z, wv.w};
#pragma unroll
            for (int i = 0; i < 4; ++i)
#pragma unroll
                for (int j = 0; j < 4; ++j)
                    acc[i][j] = fmaf(aa[i], ww[j], acc[i][j]);
        }
        if (more) {
            float* dA = As[(kt + 1) & 1];
            float* dW = Ws[(kt + 1) & 1];
#pragma unroll
            for (int e = 0; e < 8; ++e) {
                int idx = tid + e * 256, m = idx >> 5, k = idx & 31;
                dA[k * 68 + m] = pfA[e];
                dW[k * 68 + m] = pfW[e];
            }
        }
        __syncthreads();
    }
#pragma unroll
    for (int i = 0; i < 4; ++i) {
        int m = mbase + b0 + i;
#pragma unroll
        for (int j = 0; j < 4; ++j) {
            int n = n0 + nt + j;
            C[(size_t)m * ldc + n] = acc[i][j] + bias1[n] + bias2[n];
        }
    }
}
__global__ void __launch_bounds__(256) k_pre2(const float* __restrict__ W,
                                              const float* __restrict__ b1,
                                              const float* __restrict__ b2) {
    gemm64_core(g_hA, HID, W, HID, g_pre2, G4, HID, b1, b2);
}

// ---------------- tf32 mma.sync linear (proven R7/R8) ----------------
__global__ void __launch_bounds__(256, 1) k_lin_mma(const float* __restrict__ Wl) {
    extern __shared__ __align__(16) uint32_t lsm[];
    const int tid = threadIdx.x, wid = tid >> 5, lane = tid & 31;
    const int gid = lane >> 2, tig = lane & 3;
    const int m0 = blockIdx.x * 128;
    const int ks = blockIdx.y;
    const int k0b = ks * KPER;

    float acc[4][2][4];
#pragma unroll
    for (int mt = 0; mt < 4; ++mt)
#pragma unroll
        for (int nt = 0; nt < 2; ++nt)
#pragma unroll
            for (int r = 0; r < 4; ++r) acc[mt][nt][r] = 0.0f;
    {
        uint32_t* A0 = lsm;
        uint32_t* W0 = lsm + 4352;
#pragma unroll
        for (int e = 0; e < 4; ++e) {
            int idx = tid + e * 256, row = idx >> 4, c4 = idx & 15;
            float4 v = *(const float4*)(g_seq + (size_t)row * KLIN + k0b + c4 * 4);
            uint32_t* d = A0 + row * 68 + c4 * 4;
            d[0] = f2tf(v.x); d[1] = f2tf(v.y); d[2] = f2tf(v.z); d[3] = f2tf(v.w);
        }
#pragma unroll
        for (int e = 0; e < 8; ++e) {
            int idx = tid + e * 256, row = idx >> 4, c4 = idx & 15;
            float4 v = *(const float4*)(Wl + (size_t)(m0 + row) * KLIN + k0b + c4 * 4);
            uint32_t* d = W0 + row * 68 + c4 * 4;
            d[0] = f2tf(v.x); d[1] = f2tf(v.y); d[2] = f2tf(v.z); d[3] = f2tf(v.w);
        }
    }
    __syncthreads();

    for (int ch = 0; ch < LNCH; ++ch) {
        const int buf = ch & 1;
        const bool more = (ch + 1 < LNCH);
        float4 fa[4], fw[8];
        if (more) {
            int k0 = k0b + (ch + 1) * LCHUNK;
#pragma unroll
            for (int e = 0; e < 4; ++e) {
                int idx = tid + e * 256, row = idx >> 4, c4 = idx & 15;
                fa[e] = *(const float4*)(g_seq + (size_t)row * KLIN + k0 + c4 * 4);
            }
#pragma unroll
            for (int e = 0; e < 8; ++e) {
                int idx = tid + e * 256, row = idx >> 4, c4 = idx & 15;
                fw[e] = *(const float4*)(Wl + (size_t)(m0 + row) * KLIN + k0 + c4 * 4);
            }
        }
        const uint32_t* As = lsm + buf * 13056;
        const uint32_t* Ws = lsm + buf * 13056 + 4352;
#pragma unroll
        for (int kk = 0; kk < 8; ++kk) {
            uint32_t a[4][4], b[2][2];
#pragma unroll
            for (int mt = 0; mt < 4; ++mt) {
                const uint32_t* ap = As + (mt * 16 + gid) * 68 + kk * 8 + tig;
                a[mt][0] = ap[0];
                a[mt][1] = ap[8 * 68];
                a[mt][2] = ap[4];
                a[mt][3] = ap[8 * 68 + 4];
            }
#pragma unroll
            for (int nt = 0; nt < 2; ++nt) {
                const uint32_t* bp = Ws + (wid * 16 + nt * 8 + gid) * 68 + kk * 8 + tig;
                b[nt][0] = bp[0];
                b[nt][1] = bp[4];
            }
#pragma unroll
            for (int mt = 0; mt < 4; ++mt)
#pragma unroll
                for (int nt = 0; nt < 2; ++nt)
                    mma_tf32(acc[mt][nt], a[mt], b[nt]);
        }
        if (more) {
            uint32_t* A1 = lsm + (buf ^ 1) * 13056;
            uint32_t* W1 = A1 + 4352;
#pragma unroll
            for (int e = 0; e < 4; ++e) {
                int idx = tid + e * 256, row = idx >> 4, c4 = idx & 15;
                uint32_t* d = A1 + row * 68 + c4 * 4;
                d[0] = f2tf(fa[e].x); d[1] = f2tf(fa[e].y);
                d[2] = f2tf(fa[e].z); d[3] = f2tf(fa[e].w);
            }
#pragma unroll
            for (int e = 0; e < 8; ++e) {
                int idx = tid + e * 256, row = idx >> 4, c4 = idx & 15;
                uint32_t* d = W1 + row * 68 + c4 * 4;
                d[0] = f2tf(fw[e].x); d[1] = f2tf(fw[e].y);
                d[2] = f2tf(fw[e].z); d[3] = f2tf(fw[e].w);
            }
        }
        __syncthreads();
    }
#pragma unroll
    for (int mt = 0; mt < 4; ++mt) {
#pragma unroll
        for (int nt = 0; nt < 2; ++nt) {
            int brow = mt * 16 + gid;
            int m = m0 + wid * 16 + nt * 8 + 2 * tig;
            float* base0 = &g_part[((size_t)ks * BATCH + brow) * NLIN + m];
            float* base1 = &g_part[((size_t)ks * BATCH + brow + 8) * NLIN + m];
            *(float2*)base0 = make_float2(acc[mt][nt][0], acc[mt][nt][1]);
            *(float2*)base1 = make_float2(acc[mt][nt][2], acc[mt][nt][3]);
        }
    }
}

// ---------------- one LSTM time-step per launch (R13-proven staging) ----------------
__global__ void __launch_bounds__(256, 1) k_step(int layer, int t, int loadC,
                                                 int writeSeq, int writeF) {
    extern __shared__ __align__(16) uint32_t sm[];
    uint32_t* wsf = sm + WS_OFF;
    uint32_t* Ahi = sm + AHI_OFF;
    uint32_t* Alo = sm + ALO_OFF;
    float* Csm = (float*)(sm + CSM_OFF);
    float* red = (float*)(sm + RED_OFF);

    const int tid = threadIdx.x;
    const int bk = blockIdx.x;
    const int hc0 = bk * 4;
    const int lane = tid & 31, wid = tid >> 5;
    const int mg = wid >> 1, kh = wid & 1;
    const int gid = lane >> 2, tig = lane & 3;
    const int b = tid & 63, chn = (tid >> 6) & 3;
    const int hcol = hc0 + chn;

    const unsigned short* hinHi = (t & 1) ? g_hBhi16 : g_hAhi16;
    const unsigned short* hinLo = (t & 1) ? g_hBlo16 : g_hAlo16;
    unsigned short* houtHi = (t & 1) ? g_hAhi16 : g_hBhi16;
    unsigned short* houtLo = (t & 1) ? g_hAlo16 : g_hBlo16;
    float* houtF = (t & 1) ? g_hA : g_hB;
    const float* pre = layer ? (g_pre2 + b * G4 + hcol)
                             : (g_pre1 + (size_t)t * (BATCH * G4) + b * G4 + hcol);

    // stage W frags (32 KB) + h planes (2x64 KB): 4096 uint4 each -> e<16
    {
        const uint4* wsrc = (const uint4*)(g_wf[layer] + (size_t)bk * 8192);
        uint4* wdst = (uint4*)wsf;
#pragma unroll
        for (int e = 0; e < 8; ++e)
            wdst[tid + e * 256] = __ldcg(wsrc + tid + e * 256);
#pragma unroll
        for (int e = 0; e < 16; ++e) {
            int idx = tid + e * 256;
            int row = idx >> 6, c8 = idx & 63;
            uint4 vh = __ldcg((const uint4*)(hinHi + row * 512) + c8);
            uint4 vl = __ldcg((const uint4*)(hinLo + row * 512) + c8);
            *(uint4*)(Ahi + row * 260 + c8 * 4) = vh;
            *(uint4*)(Alo + row * 260 + c8 * 4) = vl;
        }
    }
    float p0 = __ldg(pre), p1 = __ldg(pre + 512);
    float p2 = __ldg(pre + 1024), p3 = __ldg(pre + 1536);
    float creg = loadC ? g_c[b * HID + hcol] : 0.0f;
    __syncthreads();

    float acc[2][4];
#pragma unroll
    for (int nt = 0; nt < 2; ++nt)
#pragma unroll
        for (int r = 0; r < 4; ++r) acc[nt][r] = 0.f;

#pragma unroll
    for (int kt = 0; kt < 16; ++kt) {
        int ktg = kh * 16 + kt;
        int abase = (mg * 16 + gid) * 260 + ktg * 8 + tig;
        uint32_t ah[4], al[4];
        ah[0] = Ahi[abase];       ah[1] = Ahi[abase + 8 * 260];
        ah[2] = Ahi[abase + 4];   ah[3] = Ahi[abase + 8 * 260 + 4];
        al[0] = Alo[abase];       al[1] = Alo[abase + 8 * 260];
        al[2] = Alo[abase + 4];   al[3] = Alo[abase + 8 * 260 + 4];
#pragma unroll
        for (int nt = 0; nt < 2; ++nt) {
            int fb = ((ktg * 2 + nt) * 2) * 64 + lane * 2;
            uint32_t bh[2], bl[2];
            *(uint2*)bh = *(const uint2*)(wsf + fb);
            *(uint2*)bl = *(const uint2*)(wsf + fb + 64);
            mma_bf16(acc[nt], ah, bh);
            mma_bf16(acc[nt], ah, bl);
            mma_bf16(acc[nt], al, bh);
        }
    }

    if (kh == 1) {
#pragma unroll
        for (int nt = 0; nt < 2; ++nt)
            *(float4*)(red + (mg * 32 + lane) * 8 + nt * 4) =
                make_float4(acc[nt][0], acc[nt][1], acc[nt][2], acc[nt][3]);
    }
    __syncthreads();
    if (kh == 0) {
#pragma unroll
        for (int nt = 0; nt < 2; ++nt) {
            float4 r4 = *(const float4*)(red + (mg * 32 + lane) * 8 + nt * 4);
            int row = mg * 16 + gid, col = nt * 8 + 2 * tig;
            Csm[row * 17 + col]           = acc[nt][0] + r4.x;
            Csm[row * 17 + col + 1]       = acc[nt][1] + r4.y;
            Csm[(row + 8) * 17 + col]     = acc[nt][2] + r4.z;
            Csm[(row + 8) * 17 + col + 1] = acc[nt][3] + r4.w;
        }
    }
    __syncthreads();

    {
        float a0 = Csm[b * 17 + 0 + chn] + p0;
        float a1 = Csm[b * 17 + 4 + chn] + p1;
        float a2 = Csm[b * 17 + 8 + chn] + p2;
        float a3 = Csm[b * 17 + 12 + chn] + p3;
        float si = 1.f / (1.f + __expf(-a0));
        float sf = 1.f / (1.f + __expf(-a1));
        float so = 1.f / (1.f + __expf(-a3));
        creg = sf * creg + si * tanhf(a2);
        float hnew = so * tanhf(creg);
        g_c[b * HID + hcol] = creg;
        __nv_bfloat16 hh = __float2bfloat16(hnew);
        __nv_bfloat16 hl = __float2bfloat16(hnew - __bfloat162float(hh));
        houtHi[b * HID + hcol] = __bfloat16_as_ushort(hh);
        houtLo[b * HID + hcol] = __bfloat16_as_ushort(hl);
        if (writeF) houtF[b * HID + hcol] = hnew;
        if (writeSeq) g_seq[(size_t)b * KLIN + t * HID + hcol] = hnew;
    }
}

extern "C" void kernel_launch(void* const* d_in, const int* in_sizes, int n_in,
                              void* d_out, int out_size) {
    const float* x    = (const float*)d_in[0];
    const float* Wih1 = (const float*)d_in[1];
    const float* Whh1 = (const float*)d_in[2];
    const float* bih1 = (const float*)d_in[3];
    const float* bhh1 = (const float*)d_in[4];
    const float* Wih2 = (const float*)d_in[5];
    const float* Whh2 = (const float*)d_in[6];
    const float* bih2 = (const float*)d_in[7];
    const float* bhh2 = (const float*)d_in[8];
    const float* Wlin = (const float*)d_in[9];
    const float* blin = (const float*)d_in[10];
    float* out = (float*)d_out;

    const int stepSmem = DSMW * 4;        // 174592
    const int linSmem  = 2 * 13056 * 4;   // 104448
    const int p1Smem   = P1SMW * 4;       // 104448
    cudaFuncSetAttribute(k_step, cudaFuncAttributeMaxDynamicSharedMemorySize, stepSmem);
    cudaFuncSetAttribute(k_lin_mma, cudaFuncAttributeMaxDynamicSharedMemorySize, linSmem);
    cudaFuncSetAttribute(k_pre1_mma, cudaFuncAttributeMaxDynamicSharedMemorySize, p1Smem);

    k_xt<<<(TIN * BATCH * FIN + 255) / 256, 256>>>(x);
    k_init<<<(BATCH * HID + 255) / 256, 256>>>();
    k_prepW<<<256, 256>>>(Whh1, Whh2);

    dim3 gpre1(G4 / 128, (TIN * BATCH) / 64);
    k_pre1_mma<<<gpre1, 256, p1Smem>>>(Wih1, bih1, bhh1);

    for (int t = 0; t < TIN; ++t)
        k_step<<<128, 256, stepSmem>>>(0, t, t > 0 ? 1 : 0, 0,
                                       (t == TIN - 1) ? 1 : 0);
    // t=127 odd -> houtF = g_hA holds final encoder h (f32); c in g_c

    dim3 gpre2(G4 / 64, 1, 1);
    k_pre2<<<gpre2, 256>>>(Wih2, bih2, bhh2);

    for (int t = 0; t < TOUTN; ++t)
        k_step<<<128, 256, stepSmem>>>(1, t, 1, 1, 0);

    dim3 glin(NLIN / 128, KSPLIT);
    k_lin_mma<<<glin, 256, linSmem>>>(Wlin);

    k_combine<<<(BATCH * NLIN + 255) / 256, 256>>>(blin, out);
}

// round 16
// speedup vs baseline: 1.6060x; 1.0980x over previous
#include <cuda_runtime.h>
#include <cuda_bf16.h>
#include <cstdint>

#define BATCH 64
#define TIN   128
#define FIN   64
#define HID   512
#define G4    2048
#define TOUTN 64
#define KLIN  32768
#define NLIN  4096

#define KSPLIT 4
#define KPER   (KLIN / KSPLIT)
#define LCHUNK 64
#define LNCH   (KPER / LCHUNK)

// k_step smem (u32 words)
#define WS_OFF  0
#define AHI_OFF 8192
#define ALO_OFF (AHI_OFF + 16640)
#define CSM_OFF (ALO_OFF + 16640)
#define RED_OFF (CSM_OFF + 1152)
#define DSMW    (RED_OFF + 1024)    // 43648 u32 = 174592 B

// k_pre1_mma smem (u32 words)
#define P1_AHI 0
#define P1_ALO 4352
#define P1_WHI 8704
#define P1_WLO 17408
#define P1SMW  26112                // 104448 B

__device__ float g_pre1[TIN * BATCH * G4];
__device__ float g_pre2[BATCH * G4];
__device__ float g_hA[BATCH * HID];
__device__ float g_hB[BATCH * HID];
__device__ unsigned short g_hAhi16[BATCH * HID];
__device__ unsigned short g_hAlo16[BATCH * HID];
__device__ unsigned short g_hBhi16[BATCH * HID];
__device__ unsigned short g_hBlo16[BATCH * HID];
__device__ float g_c[BATCH * HID];
__device__ float g_seq[BATCH * KLIN];
__device__ float g_part[KSPLIT * BATCH * NLIN];
__device__ uint32_t g_wf[2][128 * 8192];   // frag-major bf16 hi/lo W planes

__device__ __forceinline__ uint32_t f2tf(float f) {
    uint32_t u;
    asm("cvt.rna.tf32.f32 %0, %1;" : "=r"(u) : "f"(f));
    return u;
}
__device__ __forceinline__ void mma_tf32(float* c, const uint32_t* a, const uint32_t* b) {
    asm volatile(
        "mma.sync.aligned.m16n8k8.row.col.f32.tf32.tf32.f32 "
        "{%0,%1,%2,%3}, {%4,%5,%6,%7}, {%8,%9}, {%0,%1,%2,%3};"
        : "+f"(c[0]), "+f"(c[1]), "+f"(c[2]), "+f"(c[3])
        : "r"(a[0]), "r"(a[1]), "r"(a[2]), "r"(a[3]), "r"(b[0]), "r"(b[1]));
}
__device__ __forceinline__ void mma_bf16(float* c, const uint32_t* a, const uint32_t* b) {
    asm volatile(
        "mma.sync.aligned.m16n8k16.row.col.f32.bf16.bf16.f32 "
        "{%0,%1,%2,%3}, {%4,%5,%6,%7}, {%8,%9}, {%0,%1,%2,%3};"
        : "+f"(c[0]), "+f"(c[1]), "+f"(c[2]), "+f"(c[3])
        : "r"(a[0]), "r"(a[1]), "r"(a[2]), "r"(a[3]), "r"(b[0]), "r"(b[1]));
}
__device__ __forceinline__ uint32_t bf16_split_pack(float x) {
    __nv_bfloat16 h = __float2bfloat16(x);
    float hf = __bfloat162float(h);
    __nv_bfloat16 l = __float2bfloat16(x - hf);
    return (uint32_t)__bfloat16_as_ushort(h) |
           ((uint32_t)__bfloat16_as_ushort(l) << 16);
}

// ---------------- small kernels ----------------
__global__ void k_init() {
    int i = blockIdx.x * 256 + threadIdx.x;
    if (i < BATCH * HID) {
        g_hAhi16[i] = 0; g_hAlo16[i] = 0; g_c[i] = 0.0f;
    }
}
__global__ void k_combine(const float* __restrict__ blin, float* __restrict__ out) {
    int i = blockIdx.x * 256 + threadIdx.x;
    if (i < BATCH * NLIN) {
        int b = i >> 12, m = i & 4095;
        float s = blin[m];
#pragma unroll
        for (int ks = 0; ks < KSPLIT; ++ks)
            s += g_part[((size_t)ks * BATCH + b) * NLIN + m];
        out[i] = s;
    }
}

// ---------------- W frag prep (R10-verified layout) ----------------
__global__ void __launch_bounds__(256) k_prepW(const float* __restrict__ W1,
                                               const float* __restrict__ W2) {
    int layer = blockIdx.x >> 7;
    int bk = blockIdx.x & 127;
    const float* Whh = layer ? W2 : W1;
    uint32_t* dst = g_wf[layer] + (size_t)bk * 8192;
    int hc0 = bk * 4;
    for (int idx = threadIdx.x; idx < 8192; idx += 256) {
        int fragId = idx >> 6, rem = idx & 63;
        int ln = rem >> 1, rg = rem & 1;
        int plane = fragId & 1, nt = (fragId >> 1) & 1, ktile = fragId >> 2;
        int n = nt * 8 + (ln >> 2);
        int q = n >> 2, cc = n & 3;
        int k = ktile * 16 + (ln & 3) * 2 + rg * 8;
        const float* wr = Whh + (size_t)(q * HID + hc0 + cc) * HID + k;
        uint32_t p0 = bf16_split_pack(wr[0]);
        uint32_t p1 = bf16_split_pack(wr[1]);
        dst[idx] = (plane == 0) ? __byte_perm(p0, p1, 0x5410)
                                : __byte_perm(p0, p1, 0x7632);
    }
}

// ---------------- tf32 hi/lo mma pre1 (x read transposed directly) ----------------
// grid: (G4/128, TIN). blockIdx.y == t; A rows are batch b = 0..63.
__global__ void __launch_bounds__(256, 1) k_pre1_mma(const float* __restrict__ x,
                                                     const float* __restrict__ W,
                                                     const float* __restrict__ b1,
                                                     const float* __restrict__ b2) {
    extern __shared__ __align__(16) uint32_t psm[];
    uint32_t* Ahi = psm + P1_AHI;
    uint32_t* Alo = psm + P1_ALO;
    uint32_t* Whi = psm + P1_WHI;
    uint32_t* Wlo = psm + P1_WLO;
    const int tid = threadIdx.x, wid = tid >> 5, lane = tid & 31;
    const int gid = lane >> 2, tig = lane & 3;
    const int n0 = blockIdx.x * 128;
    const int tt = blockIdx.y;
    const int m0 = tt * 64;

#pragma unroll
    for (int e = 0; e < 4; ++e) {
        int idx = tid + e * 256, row = idx >> 4, c4 = idx & 15;
        float4 v = *(const float4*)(x + ((size_t)row * TIN + tt) * FIN + c4 * 4);
        uint32_t* dh = Ahi + row * 68 + c4 * 4;
        uint32_t* dl = Alo + row * 68 + c4 * 4;
        uint32_t h0 = f2tf(v.x), h1 = f2tf(v.y), h2 = f2tf(v.z), h3 = f2tf(v.w);
        dh[0] = h0; dh[1] = h1; dh[2] = h2; dh[3] = h3;
        dl[0] = f2tf(v.x - __uint_as_float(h0));
        dl[1] = f2tf(v.y - __uint_as_float(h1));
        dl[2] = f2tf(v.z - __uint_as_float(h2));
        dl[3] = f2tf(v.w - __uint_as_float(h3));
    }
#pragma unroll
    for (int e = 0; e < 8; ++e) {
        int idx = tid + e * 256, row = idx >> 4, c4 = idx & 15;
        float4 v = *(const float4*)(W + (size_t)(n0 + row) * FIN + c4 * 4);
        uint32_t* dh = Whi + row * 68 + c4 * 4;
        uint32_t* dl = Wlo + row * 68 + c4 * 4;
        uint32_t h0 = f2tf(v.x), h1 = f2tf(v.y), h2 = f2tf(v.z), h3 = f2tf(v.w);
        dh[0] = h0; dh[1] = h1; dh[2] = h2; dh[3] = h3;
        dl[0] = f2tf(v.x - __uint_as_float(h0));
        dl[1] = f2tf(v.y - __uint_as_float(h1));
        dl[2] = f2tf(v.z - __uint_as_float(h2));
        dl[3] = f2tf(v.w - __uint_as_float(h3));
    }
    __syncthreads();

    float acc[4][2][4];
#pragma unroll
    for (int mt = 0; mt < 4; ++mt)
#pragma unroll
        for (int nt = 0; nt < 2; ++nt)
#pragma unroll
            for (int r = 0; r < 4; ++r) acc[mt][nt][r] = 0.0f;

#pragma unroll
    for (int kk = 0; kk < 8; ++kk) {
        uint32_t ah[4][4], al[4][4], bh[2][2], bl[2][2];
#pragma unroll
        for (int mt = 0; mt < 4; ++mt) {
            int ab = (mt * 16 + gid) * 68 + kk * 8 + tig;
            ah[mt][0] = Ahi[ab];           ah[mt][1] = Ahi[ab + 8 * 68];
            ah[mt][2] = Ahi[ab + 4];       ah[mt][3] = Ahi[ab + 8 * 68 + 4];
            al[mt][0] = Alo[ab];           al[mt][1] = Alo[ab + 8 * 68];
            al[mt][2] = Alo[ab + 4];       al[mt][3] = Alo[ab + 8 * 68 + 4];
        }
#pragma unroll
        for (int nt = 0; nt < 2; ++nt) {
            int bb = (wid * 16 + nt * 8 + gid) * 68 + kk * 8 + tig;
            bh[nt][0] = Whi[bb];  bh[nt][1] = Whi[bb + 4];
            bl[nt][0] = Wlo[bb];  bl[nt][1] = Wlo[bb + 4];
        }
#pragma unroll
        for (int mt = 0; mt < 4; ++mt)
#pragma unroll
            for (int nt = 0; nt < 2; ++nt) {
                mma_tf32(acc[mt][nt], ah[mt], bh[nt]);
                mma_tf32(acc[mt][nt], ah[mt], bl[nt]);
                mma_tf32(acc[mt][nt], al[mt], bh[nt]);
            }
    }

#pragma unroll
    for (int mt = 0; mt < 4; ++mt) {
#pragma unroll
        for (int nt = 0; nt < 2; ++nt) {
            int m = m0 + mt * 16 + gid;
            int n = n0 + wid * 16 + nt * 8 + 2 * tig;
            float bias0 = b1[n] + b2[n], bias1v = b1[n + 1] + b2[n + 1];
            *(float2*)(g_pre1 + (size_t)m * G4 + n) =
                make_float2(acc[mt][nt][0] + bias0, acc[mt][nt][1] + bias1v);
            *(float2*)(g_pre1 + (size_t)(m + 8) * G4 + n) =
                make_float2(acc[mt][nt][2] + bias0, acc[mt][nt][3] + bias1v);
        }
    }
}

// ---------------- fp32 SIMT GEMM (pre2 only, proven) ----------------
__device__ __forceinline__ void gemm64_core(
    const float* __restrict__ A, int lda,
    const float* __restrict__ W, int ldw,
    float* __restrict__ C, int ldc, int kcount,
    const float* __restrict__ bias1, const float* __restrict__ bias2)
{
    __shared__ __align__(16) float As[2][32 * 68];
    __shared__ __align__(16) float Ws[2][32 * 68];
    const int tid = threadIdx.x;
    const int n0 = blockIdx.x * 64;
    const int mbase = blockIdx.z * 64;
    const int b0 = (tid & 15) * 4, nt = (tid >> 4) * 4;
    float acc[4][4];
#pragma unroll
    for (int i = 0; i < 4; ++i)
#pragma unroll
        for (int j = 0; j < 4; ++j) acc[i][j] = 0.0f;
    const int ntiles = kcount >> 5;
#pragma unroll
    for (int e = 0; e < 8; ++e) {
        int idx = tid + e * 256, m = idx >> 5, k = idx & 31;
        As[0][k * 68 + m] = A[(size_t)(mbase + m) * lda + k];
        Ws[0][k * 68 + m] = W[(size_t)(n0 + m) * ldw + k];
    }
    __syncthreads();
    for (int kt = 0; kt < ntiles; ++kt) {
        float pfA[8], pfW[8];
        const bool more = (kt + 1 < ntiles);
        if (more) {
            int ko = (kt + 1) << 5;
#pragma unroll
            for (int e = 0; e < 8; ++e) {
                int idx = tid + e * 256, m = idx >> 5, k = idx & 31;
                pfA[e] = A[(size_t)(mbase + m) * lda + ko + k];
                pfW[e] = W[(size_t)(n0 + m) * ldw + ko + k];
            }
        }
        const float* as = As[kt & 1];
        const float* wz = Ws[kt & 1];
#pragma unroll
        for (int k = 0; k < 32; ++k) {
            float4 av = *(const float4*)(as + k * 68 + b0);
            float4 wv = *(const float4*)(wz + k * 68 + nt);
            float aa[4] = {av.x, av.y, av.z, av.w};
            float ww[4] = {wv.x, wv.y, wv.z, wv.w};
#pragma unroll
            for (int i = 0; i < 4; ++i)
#pragma unroll
                for (int j = 0; j < 4; ++j)
                    acc[i][j] = fmaf(aa[i], ww[j], acc[i][j]);
        }
        if (more) {
            float* dA = As[(kt + 1) & 1];
            float* dW = Ws[(kt + 1) & 1];
#pragma unroll
            for (int e = 0; e < 8; ++e) {
                int idx = tid + e * 256, m = idx >> 5, k = idx & 31;
                dA[k * 68 + m] = pfA[e];
                dW[k * 68 + m] = pfW[e];
            }
        }
        __syncthreads();
    }
#pragma unroll
    for (int i = 0; i < 4; ++i) {
        int m = mbase + b0 + i;
#pragma unroll
        for (int j = 0; j < 4; ++j) {
            int n = n0 + nt + j;
            C[(size_t)m * ldc + n] = acc[i][j] + bias1[n] + bias2[n];
        }
    }
}
__global__ void __launch_bounds__(256) k_pre2(const float* __restrict__ W,
                                              const float* __restrict__ b1,
                                              const float* __restrict__ b2) {
    gemm64_core(g_hA, HID, W, HID, g_pre2, G4, HID, b1, b2);
}

// ---------------- tf32 mma.sync linear (proven R7/R8) ----------------
__global__ void __launch_bounds__(256, 1) k_lin_mma(const float* __restrict__ Wl) {
    extern __shared__ __align__(16) uint32_t lsm[];
    const int tid = threadIdx.x, wid = tid >> 5, lane = tid & 31;
    const int gid = lane >> 2, tig = lane & 3;
    const int m0 = blockIdx.x * 128;
    const int ks = blockIdx.y;
    const int k0b = ks * KPER;

    float acc[4][2][4];
#pragma unroll
    for (int mt = 0; mt < 4; ++mt)
#pragma unroll
        for (int nt = 0; nt < 2; ++nt)
#pragma unroll
            for (int r = 0; r < 4; ++r) acc[mt][nt][r] = 0.0f;
    {
        uint32_t* A0 = lsm;
        uint32_t* W0 = lsm + 4352;
#pragma unroll
        for (int e = 0; e < 4; ++e) {
            int idx = tid + e * 256, row = idx >> 4, c4 = idx & 15;
            float4 v = *(const float4*)(g_seq + (size_t)row * KLIN + k0b + c4 * 4);
            uint32_t* d = A0 + row * 68 + c4 * 4;
            d[0] = f2tf(v.x); d[1] = f2tf(v.y); d[2] = f2tf(v.z); d[3] = f2tf(v.w);
        }
#pragma unroll
        for (int e = 0; e < 8; ++e) {
            int idx = tid + e * 256, row = idx >> 4, c4 = idx & 15;
            float4 v = *(const float4*)(Wl + (size_t)(m0 + row) * KLIN + k0b + c4 * 4);
            uint32_t* d = W0 + row * 68 + c4 * 4;
            d[0] = f2tf(v.x); d[1] = f2tf(v.y); d[2] = f2tf(v.z); d[3] = f2tf(v.w);
        }
    }
    __syncthreads();

    for (int ch = 0; ch < LNCH; ++ch) {
        const int buf = ch & 1;
        const bool more = (ch + 1 < LNCH);
        float4 fa[4], fw[8];
        if (more) {
            int k0 = k0b + (ch + 1) * LCHUNK;
#pragma unroll
            for (int e = 0; e < 4; ++e) {
                int idx = tid + e * 256, row = idx >> 4, c4 = idx & 15;
                fa[e] = *(const float4*)(g_seq + (size_t)row * KLIN + k0 + c4 * 4);
            }
#pragma unroll
            for (int e = 0; e < 8; ++e) {
                int idx = tid + e * 256, row = idx >> 4, c4 = idx & 15;
                fw[e] = *(const float4*)(Wl + (size_t)(m0 + row) * KLIN + k0 + c4 * 4);
            }
        }
        const uint32_t* As = lsm + buf * 13056;
        const uint32_t* Ws = lsm + buf * 13056 + 4352;
#pragma unroll
        for (int kk = 0; kk < 8; ++kk) {
            uint32_t a[4][4], b[2][2];
#pragma unroll
            for (int mt = 0; mt < 4; ++mt) {
                const uint32_t* ap = As + (mt * 16 + gid) * 68 + kk * 8 + tig;
                a[mt][0] = ap[0];
                a[mt][1] = ap[8 * 68];
                a[mt][2] = ap[4];
                a[mt][3] = ap[8 * 68 + 4];
            }
#pragma unroll
            for (int nt = 0; nt < 2; ++nt) {
                const uint32_t* bp = Ws + (wid * 16 + nt * 8 + gid) * 68 + kk * 8 + tig;
                b[nt][0] = bp[0];
                b[nt][1] = bp[4];
            }
#pragma unroll
            for (int mt = 0; mt < 4; ++mt)
#pragma unroll
                for (int nt = 0; nt < 2; ++nt)
                    mma_tf32(acc[mt][nt], a[mt], b[nt]);
        }
        if (more) {
            uint32_t* A1 = lsm + (buf ^ 1) * 13056;
            uint32_t* W1 = A1 + 4352;
#pragma unroll
            for (int e = 0; e < 4; ++e) {
                int idx = tid + e * 256, row = idx >> 4, c4 = idx & 15;
                uint32_t* d = A1 + row * 68 + c4 * 4;
                d[0] = f2tf(fa[e].x); d[1] = f2tf(fa[e].y);
                d[2] = f2tf(fa[e].z); d[3] = f2tf(fa[e].w);
            }
#pragma unroll
            for (int e = 0; e < 8; ++e) {
                int idx = tid + e * 256, row = idx >> 4, c4 = idx & 15;
                uint32_t* d = W1 + row * 68 + c4 * 4;
                d[0] = f2tf(fw[e].x); d[1] = f2tf(fw[e].y);
                d[2] = f2tf(fw[e].z); d[3] = f2tf(fw[e].w);
            }
        }
        __syncthreads();
    }
#pragma unroll
    for (int mt = 0; mt < 4; ++mt) {
#pragma unroll
        for (int nt = 0; nt < 2; ++nt) {
            int brow = mt * 16 + gid;
            int m = m0 + wid * 16 + nt * 8 + 2 * tig;
            float* base0 = &g_part[((size_t)ks * BATCH + brow) * NLIN + m];
            float* base1 = &g_part[((size_t)ks * BATCH + brow + 8) * NLIN + m];
            *(float2*)base0 = make_float2(acc[mt][nt][0], acc[mt][nt][1]);
            *(float2*)base1 = make_float2(acc[mt][nt][2], acc[mt][nt][3]);
        }
    }
}

// ---------------- one LSTM time-step per launch, PDL-overlapped ----------------
__global__ void __launch_bounds__(256, 1) k_step(int layer, int t, int loadC,
                                                 int writeSeq, int writeF) {
    extern __shared__ __align__(16) uint32_t sm[];
    uint32_t* wsf = sm + WS_OFF;
    uint32_t* Ahi = sm + AHI_OFF;
    uint32_t* Alo = sm + ALO_OFF;
    float* Csm = (float*)(sm + CSM_OFF);
    float* red = (float*)(sm + RED_OFF);

    const int tid = threadIdx.x;
    const int bk = blockIdx.x;
    const int hc0 = bk * 4;
    const int lane = tid & 31, wid = tid >> 5;
    const int mg = wid >> 1, kh = wid & 1;
    const int gid = lane >> 2, tig = lane & 3;
    const int b = tid & 63, chn = (tid >> 6) & 3;
    const int hcol = hc0 + chn;

    const unsigned short* hinHi = (t & 1) ? g_hBhi16 : g_hAhi16;
    const unsigned short* hinLo = (t & 1) ? g_hBlo16 : g_hAlo16;
    unsigned short* houtHi = (t & 1) ? g_hAhi16 : g_hBhi16;
    unsigned short* houtLo = (t & 1) ? g_hAlo16 : g_hBlo16;
    float* houtF = (t & 1) ? g_hA : g_hB;
    const float* pre = layer ? (g_pre2 + b * G4 + hcol)
                             : (g_pre1 + (size_t)t * (BATCH * G4) + b * G4 + hcol);

    // --- predecessor-independent prologue: stage W frags (g_wf is final) ---
    {
        const uint4* wsrc = (const uint4*)(g_wf[layer] + (size_t)bk * 8192);
        uint4* wdst = (uint4*)wsf;
#pragma unroll
        for (int e = 0; e < 8; ++e)
            wdst[tid + e * 256] = __ldcg(wsrc + tid + e * 256);
    }

    // --- wait for predecessor completion (PDL) before touching h/c/pre ---
    cudaGridDependencySynchronize();

#pragma unroll
    for (int e = 0; e < 16; ++e) {
        int idx = tid + e * 256;
        int row = idx >> 6, c8 = idx & 63;
        uint4 vh = __ldcg((const uint4*)(hinHi + row * 512) + c8);
        uint4 vl = __ldcg((const uint4*)(hinLo + row * 512) + c8);
        *(uint4*)(Ahi + row * 260 + c8 * 4) = vh;
        *(uint4*)(Alo + row * 260 + c8 * 4) = vl;
    }
    float p0 = __ldg(pre), p1 = __ldg(pre + 512);
    float p2 = __ldg(pre + 1024), p3 = __ldg(pre + 1536);
    float creg = loadC ? g_c[b * HID + hcol] : 0.0f;
    __syncthreads();

    float acc[2][4];
#pragma unroll
    for (int nt = 0; nt < 2; ++nt)
#pragma unroll
        for (int r = 0; r < 4; ++r) acc[nt][r] = 0.f;

#pragma unroll
    for (int kt = 0; kt < 16; ++kt) {
        int ktg = kh * 16 + kt;
        int abase = (mg * 16 + gid) * 260 + ktg * 8 + tig;
        uint32_t ah[4], al[4];
        ah[0] = Ahi[abase];       ah[1] = Ahi[abase + 8 * 260];
        ah[2] = Ahi[abase + 4];   ah[3] = Ahi[abase + 8 * 260 + 4];
        al[0] = Alo[abase];       al[1] = Alo[abase + 8 * 260];
        al[2] = Alo[abase + 4];   al[3] = Alo[abase + 8 * 260 + 4];
#pragma unroll
        for (int nt = 0; nt < 2; ++nt) {
            int fb = ((ktg * 2 + nt) * 2) * 64 + lane * 2;
            uint32_t bh[2], bl[2];
            *(uint2*)bh = *(const uint2*)(wsf + fb);
            *(uint2*)bl = *(const uint2*)(wsf + fb + 64);
            mma_bf16(acc[nt], ah, bh);
            mma_bf16(acc[nt], ah, bl);
            mma_bf16(acc[nt], al, bh);
        }
    }

    if (kh == 1) {
#pragma unroll
        for (int nt = 0; nt < 2; ++nt)
            *(float4*)(red + (mg * 32 + lane) * 8 + nt * 4) =
                make_float4(acc[nt][0], acc[nt][1], acc[nt][2], acc[nt][3]);
    }
    __syncthreads();
    if (kh == 0) {
#pragma unroll
        for (int nt = 0; nt < 2; ++nt) {
            float4 r4 = *(const float4*)(red + (mg * 32 + lane) * 8 + nt * 4);
            int row = mg * 16 + gid, col = nt * 8 + 2 * tig;
            Csm[row * 17 + col]           = acc[nt][0] + r4.x;
            Csm[row * 17 + col + 1]       = acc[nt][1] + r4.y;
            Csm[(row + 8) * 17 + col]     = acc[nt][2] + r4.z;
            Csm[(row + 8) * 17 + col + 1] = acc[nt][3] + r4.w;
        }
    }
    __syncthreads();

    // let the successor grid launch & run its W-staging under our epilogue
    cudaTriggerProgrammaticLaunchCompletion();

    {
        float a0 = Csm[b * 17 + 0 + chn] + p0;
        float a1 = Csm[b * 17 + 4 + chn] + p1;
        float a2 = Csm[b * 17 + 8 + chn] + p2;
        float a3 = Csm[b * 17 + 12 + chn] + p3;
        float si = 1.f / (1.f + __expf(-a0));
        float sf = 1.f / (1.f + __expf(-a1));
        float so = 1.f / (1.f + __expf(-a3));
        creg = sf * creg + si * tanhf(a2);
        float hnew = so * tanhf(creg);
        g_c[b * HID + hcol] = creg;
        __nv_bfloat16 hh = __float2bfloat16(hnew);
        __nv_bfloat16 hl = __float2bfloat16(hnew - __bfloat162float(hh));
        houtHi[b * HID + hcol] = __bfloat16_as_ushort(hh);
        houtLo[b * HID + hcol] = __bfloat16_as_ushort(hl);
        if (writeF) houtF[b * HID + hcol] = hnew;
        if (writeSeq) g_seq[(size_t)b * KLIN + t * HID + hcol] = hnew;
    }
}

extern "C" void kernel_launch(void* const* d_in, const int* in_sizes, int n_in,
                              void* d_out, int out_size) {
    const float* x    = (const float*)d_in[0];
    const float* Wih1 = (const float*)d_in[1];
    const float* Whh1 = (const float*)d_in[2];
    const float* bih1 = (const float*)d_in[3];
    const float* bhh1 = (const float*)d_in[4];
    const float* Wih2 = (const float*)d_in[5];
    const float* Whh2 = (const float*)d_in[6];
    const float* bih2 = (const float*)d_in[7];
    const float* bhh2 = (const float*)d_in[8];
    const float* Wlin = (const float*)d_in[9];
    const float* blin = (const float*)d_in[10];
    float* out = (float*)d_out;

    const int stepSmem = DSMW * 4;        // 174592
    const int linSmem  = 2 * 13056 * 4;   // 104448
    const int p1Smem   = P1SMW * 4;       // 104448
    cudaFuncSetAttribute(k_step, cudaFuncAttributeMaxDynamicSharedMemorySize, stepSmem);
    cudaFuncSetAttribute(k_lin_mma, cudaFuncAttributeMaxDynamicSharedMemorySize, linSmem);
    cudaFuncSetAttribute(k_pre1_mma, cudaFuncAttributeMaxDynamicSharedMemorySize, p1Smem);

    k_init<<<(BATCH * HID + 255) / 256, 256>>>();
    k_prepW<<<256, 256>>>(Whh1, Whh2);

    dim3 gpre1(G4 / 128, TIN);
    k_pre1_mma<<<gpre1, 256, p1Smem>>>(x, Wih1, bih1, bhh1);

    // PDL launch config for the step chain
    cudaLaunchAttribute pdlAttr[1];
    pdlAttr[0].id = cudaLaunchAttributeProgrammaticStreamSerialization;
    pdlAttr[0].val.programmaticStreamSerializationAllowed = 1;
    cudaLaunchConfig_t cfg = {};
    cfg.gridDim = dim3(128, 1, 1);
    cfg.blockDim = dim3(256, 1, 1);
    cfg.dynamicSmemBytes = stepSmem;
    cfg.stream = 0;
    cfg.attrs = pdlAttr;
    cfg.numAttrs = 1;

    for (int t = 0; t < TIN; ++t)
        cudaLaunchKernelEx(&cfg, k_step, 0, t, t > 0 ? 1 : 0, 0,
                           (t == TIN - 1) ? 1 : 0);
    // t=127 odd -> houtF = g_hA holds final encoder h (f32); c in g_c

    dim3 gpre2(G4 / 64, 1, 1);
    k_pre2<<<gpre2, 256>>>(Wih2, bih2, bhh2);

    for (int t = 0; t < TOUTN; ++t)
        cudaLaunchKernelEx(&cfg, k_step, 1, t, 1, 1, 0);

    dim3 glin(NLIN / 128, KSPLIT);
    k_lin_mma<<<glin, 256, linSmem>>>(Wlin);

    k_combine<<<(BATCH * NLIN + 255) / 256, 256>>>(blin, out);
}